// round 1
// baseline (speedup 1.0000x reference)
#include <cuda_runtime.h>
#include <cstdint>
#include <cstddef>

// Problem constants (LowFER)
#define BB 256          // batch
#define VV 400000       // vocab
#define D1 128
#define PP 64           // D1/2
#define KK 30
#define TT 20
#define BN_EPS 1e-5f
#define FACTOR 0.040824829046386304f   // 1/sqrt(K*T) = 1/sqrt(600)

// Scratch for x (K x B), static device global (no allocations allowed)
__device__ float g_x[KK * BB];

// ---------------- packed f32x2 helpers ----------------
__device__ __forceinline__ unsigned long long pk2(float lo, float hi) {
    unsigned long long r;
    asm("mov.b64 %0, {%1, %2};" : "=l"(r) : "f"(lo), "f"(hi));
    return r;
}
__device__ __forceinline__ void upk2(unsigned long long v, float& lo, float& hi) {
    asm("mov.b64 {%0, %1}, %2;" : "=f"(lo), "=f"(hi) : "l"(v));
}
__device__ __forceinline__ unsigned long long ffma2(unsigned long long a,
                                                    unsigned long long b,
                                                    unsigned long long c) {
    unsigned long long d;
    asm("fma.rn.f32x2 %0, %1, %2, %3;" : "=l"(d) : "l"(a), "l"(b), "l"(c));
    return d;
}
// sigmoid via ex2 + rcp (high accuracy, 2 MUFU)
__device__ __forceinline__ float fast_sigmoid(float z) {
    float e;
    asm("ex2.approx.f32 %0, %1;" : "=f"(e) : "f"(-z * 1.4426950408889634f));
    float r;
    asm("rcp.approx.f32 %0, %1;" : "=f"(r) : "f"(1.0f + e));
    return r;
}

// ---------------- Kernel 1: compute x (B x K) ----------------
// One block per batch element b, 64 threads.
__global__ void prep_kernel(const int* __restrict__ e1_idx, const int* __restrict__ r_idx,
                            const float* __restrict__ E,   const float* __restrict__ R,
                            const float* __restrict__ proj, const int* __restrict__ idx,
                            const float* __restrict__ g0, const float* __restrict__ b0,
                            const float* __restrict__ m0, const float* __restrict__ v0,
                            const float* __restrict__ g1, const float* __restrict__ b1,
                            const float* __restrict__ m1, const float* __restrict__ v1)
{
    __shared__ float e1s[D1];
    __shared__ float rrs[D1];
    __shared__ float ses[PP];
    __shared__ float srs[PP];

    const int t = threadIdx.x;     // 0..63
    const int b = blockIdx.x;      // 0..255

    const int ei = e1_idx[b];
    const int ri = r_idx[b];

    #pragma unroll
    for (int j = 0; j < 2; j++) {
        const int d = t + j * 64;
        float ev = E[(size_t)ei * D1 + d];
        e1s[d] = (ev - m0[d]) * rsqrtf(v0[d] + BN_EPS) * g0[d] + b0[d];
        rrs[d] = R[(size_t)ri * D1 + d];
    }
    __syncthreads();

    // se[p] = sum_d e1[d]*proj[d][p] ; sr[p] likewise. proj is (D1, P) row-major.
    float sa = 0.f, sb = 0.f;
    #pragma unroll 4
    for (int d = 0; d < D1; d++) {
        const float p = proj[d * PP + t];
        sa = fmaf(e1s[d], p, sa);
        sb = fmaf(rrs[d], p, sb);
    }
    ses[t] = sa;
    srs[t] = sb;
    __syncthreads();

    float x = 0.f;
    if (t < KK) {
        float y = 0.f;
        #pragma unroll
        for (int tt = 0; tt < TT; tt++) {
            const int ia = idx[(t * TT + tt) * 2 + 0];
            const int ib = idx[(t * TT + tt) * 2 + 1];
            y = fmaf(ses[ia], srs[ib], y);
        }
        y *= FACTOR;
        const float sg = (y > 0.f) ? 1.f : ((y < 0.f) ? -1.f : 0.f);
        x = sg * sqrtf(fabsf(y) + 1e-12f);
    }

    // L2-norm over K within warp 0 (lanes 30,31 contribute 0)
    if (t < 32) {
        float ss = x * x;
        #pragma unroll
        for (int o = 16; o; o >>= 1) ss += __shfl_xor_sync(0xffffffffu, ss, o);
        const float nrm = sqrtf(ss);
        float xn = x / fmaxf(nrm, 1e-12f);
        if (t < KK) {
            xn = (xn - m1[t]) * rsqrtf(v1[t] + BN_EPS) * g1[t] + b1[t];
            g_x[t * BB + b] = xn;   // layout [k][b] for vectorized smem reads
        }
    }
}

// ---------------- Kernel 2: out[b][v] = sigmoid( sum_k x[b][k] * E[v][k] ) ----------------
// 1 v per thread; 16 b per pass; packed f32x2 FMAs; x pairs loaded pre-packed via LDS.128.
__global__ __launch_bounds__(256, 2)
void main_kernel(const float* __restrict__ E, float* __restrict__ out)
{
    __shared__ float xs[KK * BB];   // 30 KB, layout [k][b]

    const int tid = threadIdx.x;
    for (int i = tid; i < KK * BB; i += 256) xs[i] = g_x[i];

    const int v = blockIdx.x * 256 + tid;

    unsigned long long ed[KK];      // (e[k], e[k]) packed, 60 regs
    if (v < VV) {
        const float4* Ep = reinterpret_cast<const float4*>(E + (size_t)v * D1);
        float e[32];
        #pragma unroll
        for (int q = 0; q < 8; q++) {
            float4 f = Ep[q];
            e[q * 4 + 0] = f.x; e[q * 4 + 1] = f.y;
            e[q * 4 + 2] = f.z; e[q * 4 + 3] = f.w;
        }
        #pragma unroll
        for (int k = 0; k < KK; k++) ed[k] = pk2(e[k], e[k]);
    }
    __syncthreads();
    if (v >= VV) return;

    #pragma unroll 1
    for (int bp = 0; bp < BB; bp += 16) {
        unsigned long long acc[8];
        #pragma unroll
        for (int j = 0; j < 8; j++) acc[j] = 0ull;   // (0.f, 0.f)

        #pragma unroll
        for (int k = 0; k < KK; k++) {
            // 16 consecutive b values for this k = 4x LDS.128; each u64 is
            // already an aligned (x[b], x[b+1]) f32x2 pair — no packing movs.
            const ulonglong2* xp =
                reinterpret_cast<const ulonglong2*>(&xs[k * BB + bp]);
            const ulonglong2 u0 = xp[0];
            const ulonglong2 u1 = xp[1];
            const ulonglong2 u2 = xp[2];
            const ulonglong2 u3 = xp[3];
            acc[0] = ffma2(u0.x, ed[k], acc[0]);
            acc[1] = ffma2(u0.y, ed[k], acc[1]);
            acc[2] = ffma2(u1.x, ed[k], acc[2]);
            acc[3] = ffma2(u1.y, ed[k], acc[3]);
            acc[4] = ffma2(u2.x, ed[k], acc[4]);
            acc[5] = ffma2(u2.y, ed[k], acc[5]);
            acc[6] = ffma2(u3.x, ed[k], acc[6]);
            acc[7] = ffma2(u3.y, ed[k], acc[7]);
        }

        #pragma unroll
        for (int j = 0; j < 8; j++) {
            float lo, hi;
            upk2(acc[j], lo, hi);
            out[(size_t)(bp + 2 * j)     * VV + v] = fast_sigmoid(lo);
            out[(size_t)(bp + 2 * j + 1) * VV + v] = fast_sigmoid(hi);
        }
    }
}

// ---------------- launch ----------------
extern "C" void kernel_launch(void* const* d_in, const int* in_sizes, int n_in,
                              void* d_out, int out_size)
{
    (void)in_sizes; (void)n_in; (void)out_size;
    const int*   e1_idx = (const int*)  d_in[0];
    const int*   r_idx  = (const int*)  d_in[1];
    const float* E      = (const float*)d_in[2];
    const float* R      = (const float*)d_in[3];
    const float* proj   = (const float*)d_in[4];
    const int*   idx    = (const int*)  d_in[5];
    const float* g0     = (const float*)d_in[6];
    const float* b0     = (const float*)d_in[7];
    const float* m0     = (const float*)d_in[8];
    const float* v0     = (const float*)d_in[9];
    const float* g1     = (const float*)d_in[10];
    const float* b1     = (const float*)d_in[11];
    const float* m1     = (const float*)d_in[12];
    const float* v1     = (const float*)d_in[13];
    float*       out    = (float*)d_out;

    prep_kernel<<<BB, 64>>>(e1_idx, r_idx, E, R, proj, idx,
                            g0, b0, m0, v0, g1, b1, m1, v1);

    const int grid = (VV + 255) / 256;   // 1563
    main_kernel<<<grid, 256>>>(E, out);
}

// round 2
// speedup vs baseline: 1.1985x; 1.1985x over previous
#include <cuda_runtime.h>
#include <cstdint>
#include <cstddef>

// Problem constants (LowFER)
#define BB 256          // batch
#define VV 400000       // vocab
#define D1 128
#define PP 64           // D1/2
#define KK 30
#define TT 20
#define BN_EPS 1e-5f
#define FACTOR 0.040824829046386304f   // 1/sqrt(K*T) = 1/sqrt(600)

// Scratch for x (K x B), static device global (no allocations allowed)
__device__ float g_x[KK * BB];

// ---------------- packed f32x2 helpers ----------------
__device__ __forceinline__ unsigned long long pk2(float lo, float hi) {
    unsigned long long r;
    asm("mov.b64 %0, {%1, %2};" : "=l"(r) : "f"(lo), "f"(hi));
    return r;
}
__device__ __forceinline__ void upk2(unsigned long long v, float& lo, float& hi) {
    asm("mov.b64 {%0, %1}, %2;" : "=f"(lo), "=f"(hi) : "l"(v));
}
__device__ __forceinline__ unsigned long long ffma2(unsigned long long a,
                                                    unsigned long long b,
                                                    unsigned long long c) {
    unsigned long long d;
    asm("fma.rn.f32x2 %0, %1, %2, %3;" : "=l"(d) : "l"(a), "l"(b), "l"(c));
    return d;
}
// sigmoid via ex2 + rcp (high accuracy, 2 MUFU)
__device__ __forceinline__ float fast_sigmoid(float z) {
    float e;
    asm("ex2.approx.f32 %0, %1;" : "=f"(e) : "f"(-z * 1.4426950408889634f));
    float r;
    asm("rcp.approx.f32 %0, %1;" : "=f"(r) : "f"(1.0f + e));
    return r;
}

// ---------------- Kernel 1: compute x (B x K) ----------------
// One block per batch element b, 64 threads.
__global__ void prep_kernel(const int* __restrict__ e1_idx, const int* __restrict__ r_idx,
                            const float* __restrict__ E,   const float* __restrict__ R,
                            const float* __restrict__ proj, const int* __restrict__ idx,
                            const float* __restrict__ g0, const float* __restrict__ b0,
                            const float* __restrict__ m0, const float* __restrict__ v0,
                            const float* __restrict__ g1, const float* __restrict__ b1,
                            const float* __restrict__ m1, const float* __restrict__ v1)
{
    __shared__ float e1s[D1];
    __shared__ float rrs[D1];
    __shared__ float ses[PP];
    __shared__ float srs[PP];

    const int t = threadIdx.x;     // 0..63
    const int b = blockIdx.x;      // 0..255

    const int ei = e1_idx[b];
    const int ri = r_idx[b];

    #pragma unroll
    for (int j = 0; j < 2; j++) {
        const int d = t + j * 64;
        float ev = E[(size_t)ei * D1 + d];
        e1s[d] = (ev - m0[d]) * rsqrtf(v0[d] + BN_EPS) * g0[d] + b0[d];
        rrs[d] = R[(size_t)ri * D1 + d];
    }
    __syncthreads();

    // se[p] = sum_d e1[d]*proj[d][p] ; sr[p] likewise. proj is (D1, P) row-major.
    float sa = 0.f, sb = 0.f;
    #pragma unroll 4
    for (int d = 0; d < D1; d++) {
        const float p = proj[d * PP + t];
        sa = fmaf(e1s[d], p, sa);
        sb = fmaf(rrs[d], p, sb);
    }
    ses[t] = sa;
    srs[t] = sb;
    __syncthreads();

    float x = 0.f;
    if (t < KK) {
        float y = 0.f;
        #pragma unroll
        for (int tt = 0; tt < TT; tt++) {
            const int ia = idx[(t * TT + tt) * 2 + 0];
            const int ib = idx[(t * TT + tt) * 2 + 1];
            y = fmaf(ses[ia], srs[ib], y);
        }
        y *= FACTOR;
        const float sg = (y > 0.f) ? 1.f : ((y < 0.f) ? -1.f : 0.f);
        x = sg * sqrtf(fabsf(y) + 1e-12f);
    }

    // L2-norm over K within warp 0 (lanes 30,31 contribute 0)
    if (t < 32) {
        float ss = x * x;
        #pragma unroll
        for (int o = 16; o; o >>= 1) ss += __shfl_xor_sync(0xffffffffu, ss, o);
        const float nrm = sqrtf(ss);
        float xn = x / fmaxf(nrm, 1e-12f);
        if (t < KK) {
            xn = (xn - m1[t]) * rsqrtf(v1[t] + BN_EPS) * g1[t] + b1[t];
            g_x[t * BB + b] = xn;   // layout [k][b] for vectorized smem reads
        }
    }
}

// ---------------- Kernel 2: out[b][v] = sigmoid( sum_k x[b][k] * E[v][k] ) ----------------
// 2 v-columns per thread (v, v+128): each LDS.128 of packed x pairs feeds
// FOUR FFMA2 (two E register sets reuse the same x load) -> LDS issue rate
// halves vs round-1, unblocking the FMA pipe.
__global__ __launch_bounds__(128, 2)
void main_kernel(const float* __restrict__ E, float* __restrict__ out)
{
    __shared__ float xs[KK * BB];   // 30 KB, layout [k][b]

    const int tid = threadIdx.x;
    #pragma unroll
    for (int i = 0; i < (KK * BB) / 128; i++)
        xs[i * 128 + tid] = g_x[i * 128 + tid];

    const int v0 = blockIdx.x * 256 + tid;        // always < VV (grid sized so)
    const int v1 = v0 + 128;
    const bool has1 = (v1 < VV);

    unsigned long long ed0[KK];     // (e0[k], e0[k]) packed, 60 regs
    unsigned long long ed1[KK];     // (e1[k], e1[k]) packed, 60 regs
    {
        const float4* Ep0 = reinterpret_cast<const float4*>(E + (size_t)v0 * D1);
        float e[32];
        #pragma unroll
        for (int q = 0; q < 8; q++) {
            float4 f = Ep0[q];
            e[q * 4 + 0] = f.x; e[q * 4 + 1] = f.y;
            e[q * 4 + 2] = f.z; e[q * 4 + 3] = f.w;
        }
        #pragma unroll
        for (int k = 0; k < KK; k++) ed0[k] = pk2(e[k], e[k]);

        if (has1) {
            const float4* Ep1 = reinterpret_cast<const float4*>(E + (size_t)v1 * D1);
            #pragma unroll
            for (int q = 0; q < 8; q++) {
                float4 f = Ep1[q];
                e[q * 4 + 0] = f.x; e[q * 4 + 1] = f.y;
                e[q * 4 + 2] = f.z; e[q * 4 + 3] = f.w;
            }
        } else {
            #pragma unroll
            for (int q = 0; q < 32; q++) e[q] = 0.f;
        }
        #pragma unroll
        for (int k = 0; k < KK; k++) ed1[k] = pk2(e[k], e[k]);
    }
    __syncthreads();

    #pragma unroll 1
    for (int bp = 0; bp < BB; bp += 16) {
        unsigned long long a0[8], a1[8];
        #pragma unroll
        for (int j = 0; j < 8; j++) { a0[j] = 0ull; a1[j] = 0ull; }

        #pragma unroll
        for (int k = 0; k < KK; k++) {
            const ulonglong2* xp =
                reinterpret_cast<const ulonglong2*>(&xs[k * BB + bp]);
            const ulonglong2 u0 = xp[0];
            const ulonglong2 u1 = xp[1];
            const ulonglong2 u2 = xp[2];
            const ulonglong2 u3 = xp[3];
            a0[0] = ffma2(u0.x, ed0[k], a0[0]);  a1[0] = ffma2(u0.x, ed1[k], a1[0]);
            a0[1] = ffma2(u0.y, ed0[k], a0[1]);  a1[1] = ffma2(u0.y, ed1[k], a1[1]);
            a0[2] = ffma2(u1.x, ed0[k], a0[2]);  a1[2] = ffma2(u1.x, ed1[k], a1[2]);
            a0[3] = ffma2(u1.y, ed0[k], a0[3]);  a1[3] = ffma2(u1.y, ed1[k], a1[3]);
            a0[4] = ffma2(u2.x, ed0[k], a0[4]);  a1[4] = ffma2(u2.x, ed1[k], a1[4]);
            a0[5] = ffma2(u2.y, ed0[k], a0[5]);  a1[5] = ffma2(u2.y, ed1[k], a1[5]);
            a0[6] = ffma2(u3.x, ed0[k], a0[6]);  a1[6] = ffma2(u3.x, ed1[k], a1[6]);
            a0[7] = ffma2(u3.y, ed0[k], a0[7]);  a1[7] = ffma2(u3.y, ed1[k], a1[7]);
        }

        #pragma unroll
        for (int j = 0; j < 8; j++) {
            float lo, hi;
            upk2(a0[j], lo, hi);
            out[(size_t)(bp + 2 * j)     * VV + v0] = fast_sigmoid(lo);
            out[(size_t)(bp + 2 * j + 1) * VV + v0] = fast_sigmoid(hi);
        }
        if (has1) {
            #pragma unroll
            for (int j = 0; j < 8; j++) {
                float lo, hi;
                upk2(a1[j], lo, hi);
                out[(size_t)(bp + 2 * j)     * VV + v1] = fast_sigmoid(lo);
                out[(size_t)(bp + 2 * j + 1) * VV + v1] = fast_sigmoid(hi);
            }
        }
    }
}

// ---------------- launch ----------------
extern "C" void kernel_launch(void* const* d_in, const int* in_sizes, int n_in,
                              void* d_out, int out_size)
{
    (void)in_sizes; (void)n_in; (void)out_size;
    const int*   e1_idx = (const int*)  d_in[0];
    const int*   r_idx  = (const int*)  d_in[1];
    const float* E      = (const float*)d_in[2];
    const float* R      = (const float*)d_in[3];
    const float* proj   = (const float*)d_in[4];
    const int*   idx    = (const int*)  d_in[5];
    const float* g0     = (const float*)d_in[6];
    const float* b0     = (const float*)d_in[7];
    const float* m0     = (const float*)d_in[8];
    const float* v0     = (const float*)d_in[9];
    const float* g1     = (const float*)d_in[10];
    const float* b1     = (const float*)d_in[11];
    const float* m1     = (const float*)d_in[12];
    const float* v1     = (const float*)d_in[13];
    float*       out    = (float*)d_out;

    prep_kernel<<<BB, 64>>>(e1_idx, r_idx, E, R, proj, idx,
                            g0, b0, m0, v0, g1, b1, m1, v1);

    // 256 v-columns per block (128 threads x 2 v each)
    const int grid = (VV + 255) / 256;   // 1563
    main_kernel<<<grid, 128>>>(E, out);
}

// round 3
// speedup vs baseline: 1.2507x; 1.0435x over previous
#include <cuda_runtime.h>
#include <cstdint>
#include <cstddef>

// Problem constants (LowFER)
#define BB 256          // batch
#define VV 400000       // vocab
#define D1 128
#define PP 64           // D1/2
#define KK 30
#define TT 20
#define BN_EPS 1e-5f
#define FACTOR 0.040824829046386304f   // 1/sqrt(K*T) = 1/sqrt(600)

// Scratch for x (K x B), static device global (no allocations allowed)
__device__ float g_x[KK * BB];

// ---------------- packed f32x2 helpers ----------------
// volatile: prevent LICM hoisting the per-k splats out of the bp loop
// (that would re-inflate live registers to the round-2 level).
__device__ __forceinline__ unsigned long long pk2(float lo, float hi) {
    unsigned long long r;
    asm volatile("mov.b64 %0, {%1, %2};" : "=l"(r) : "f"(lo), "f"(hi));
    return r;
}
__device__ __forceinline__ void upk2(unsigned long long v, float& lo, float& hi) {
    asm("mov.b64 {%0, %1}, %2;" : "=f"(lo), "=f"(hi) : "l"(v));
}
__device__ __forceinline__ unsigned long long ffma2(unsigned long long a,
                                                    unsigned long long b,
                                                    unsigned long long c) {
    unsigned long long d;
    asm("fma.rn.f32x2 %0, %1, %2, %3;" : "=l"(d) : "l"(a), "l"(b), "l"(c));
    return d;
}
// sigmoid via ex2 + rcp (high accuracy, 2 MUFU)
__device__ __forceinline__ float fast_sigmoid(float z) {
    float e;
    asm("ex2.approx.f32 %0, %1;" : "=f"(e) : "f"(-z * 1.4426950408889634f));
    float r;
    asm("rcp.approx.f32 %0, %1;" : "=f"(r) : "f"(1.0f + e));
    return r;
}

// ---------------- Kernel 1: compute x (B x K) ----------------
// One block per batch element b, 64 threads.
__global__ void prep_kernel(const int* __restrict__ e1_idx, const int* __restrict__ r_idx,
                            const float* __restrict__ E,   const float* __restrict__ R,
                            const float* __restrict__ proj, const int* __restrict__ idx,
                            const float* __restrict__ g0, const float* __restrict__ b0,
                            const float* __restrict__ m0, const float* __restrict__ v0,
                            const float* __restrict__ g1, const float* __restrict__ b1,
                            const float* __restrict__ m1, const float* __restrict__ v1)
{
    __shared__ float e1s[D1];
    __shared__ float rrs[D1];
    __shared__ float ses[PP];
    __shared__ float srs[PP];

    const int t = threadIdx.x;     // 0..63
    const int b = blockIdx.x;      // 0..255

    const int ei = e1_idx[b];
    const int ri = r_idx[b];

    #pragma unroll
    for (int j = 0; j < 2; j++) {
        const int d = t + j * 64;
        float ev = E[(size_t)ei * D1 + d];
        e1s[d] = (ev - m0[d]) * rsqrtf(v0[d] + BN_EPS) * g0[d] + b0[d];
        rrs[d] = R[(size_t)ri * D1 + d];
    }
    __syncthreads();

    // se[p] = sum_d e1[d]*proj[d][p] ; sr[p] likewise. proj is (D1, P) row-major.
    float sa = 0.f, sb = 0.f;
    #pragma unroll 4
    for (int d = 0; d < D1; d++) {
        const float p = proj[d * PP + t];
        sa = fmaf(e1s[d], p, sa);
        sb = fmaf(rrs[d], p, sb);
    }
    ses[t] = sa;
    srs[t] = sb;
    __syncthreads();

    float x = 0.f;
    if (t < KK) {
        float y = 0.f;
        #pragma unroll
        for (int tt = 0; tt < TT; tt++) {
            const int ia = idx[(t * TT + tt) * 2 + 0];
            const int ib = idx[(t * TT + tt) * 2 + 1];
            y = fmaf(ses[ia], srs[ib], y);
        }
        y *= FACTOR;
        const float sg = (y > 0.f) ? 1.f : ((y < 0.f) ? -1.f : 0.f);
        x = sg * sqrtf(fabsf(y) + 1e-12f);
    }

    // L2-norm over K within warp 0 (lanes 30,31 contribute 0)
    if (t < 32) {
        float ss = x * x;
        #pragma unroll
        for (int o = 16; o; o >>= 1) ss += __shfl_xor_sync(0xffffffffu, ss, o);
        const float nrm = sqrtf(ss);
        float xn = x / fmaxf(nrm, 1e-12f);
        if (t < KK) {
            xn = (xn - m1[t]) * rsqrtf(v1[t] + BN_EPS) * g1[t] + b1[t];
            g_x[t * BB + b] = xn;   // layout [k][b] for vectorized smem reads
        }
    }
}

// ---------------- Kernel 2: out[b][v] = sigmoid( sum_k x[b][k] * E[v][k] ) ----------------
// Each thread owns ADJACENT v-pair (v0, v0+1).
//  - E rows held as 60 scalar regs; (e,e) splats generated per-k with mov.b64
//    (trades 120 persistent regs for cheap ALU movs -> 16 warps/SM).
//  - x pairs streamed pre-packed from smem via LDS.128 (broadcast).
//  - epilogue recombines the two v-accumulators into float2 stores (STG.64,
//    coalesced 256B/warp) -> store instruction count halves.
__global__ __launch_bounds__(128, 4)
void main_kernel(const float* __restrict__ E, float* __restrict__ out)
{
    __shared__ float xs[KK * BB];   // 30 KB, layout [k][b]

    const int tid = threadIdx.x;
    #pragma unroll
    for (int i = 0; i < (KK * BB) / 128; i++)
        xs[i * 128 + tid] = g_x[i * 128 + tid];
    __syncthreads();

    const int v0 = blockIdx.x * 256 + 2 * tid;   // even; v1 = v0+1
    if (v0 >= VV) return;                        // (after syncthreads: safe)

    // Load E rows v0 and v0+1, first 30 entries each (7 x float4 + 1 x float2)
    float e0[KK], e1[KK];
    {
        const float4* p0 = reinterpret_cast<const float4*>(E + (size_t)v0 * D1);
        const float4* p1 = reinterpret_cast<const float4*>(E + (size_t)(v0 + 1) * D1);
        #pragma unroll
        for (int q = 0; q < 7; q++) {
            float4 f = p0[q];
            e0[q * 4 + 0] = f.x; e0[q * 4 + 1] = f.y;
            e0[q * 4 + 2] = f.z; e0[q * 4 + 3] = f.w;
            f = p1[q];
            e1[q * 4 + 0] = f.x; e1[q * 4 + 1] = f.y;
            e1[q * 4 + 2] = f.z; e1[q * 4 + 3] = f.w;
        }
        float2 t0 = reinterpret_cast<const float2*>(p0)[14];
        e0[28] = t0.x; e0[29] = t0.y;
        t0 = reinterpret_cast<const float2*>(p1)[14];
        e1[28] = t0.x; e1[29] = t0.y;
    }

    #pragma unroll 1
    for (int bp = 0; bp < BB; bp += 8) {
        // b-packed accumulators: a0[j] = (out[v0] for b-pair j), a1[j] = same for v1
        unsigned long long a0[4], a1[4];
        #pragma unroll
        for (int j = 0; j < 4; j++) { a0[j] = 0ull; a1[j] = 0ull; }

        #pragma unroll
        for (int k = 0; k < KK; k++) {
            const ulonglong2* xp =
                reinterpret_cast<const ulonglong2*>(&xs[k * BB + bp]);
            const ulonglong2 u0 = xp[0];   // (x_b0,x_b1),(x_b2,x_b3)
            const ulonglong2 u1 = xp[1];   // (x_b4,x_b5),(x_b6,x_b7)
            const unsigned long long d0 = pk2(e0[k], e0[k]);
            const unsigned long long d1 = pk2(e1[k], e1[k]);
            a0[0] = ffma2(u0.x, d0, a0[0]);  a1[0] = ffma2(u0.x, d1, a1[0]);
            a0[1] = ffma2(u0.y, d0, a0[1]);  a1[1] = ffma2(u0.y, d1, a1[1]);
            a0[2] = ffma2(u1.x, d0, a0[2]);  a1[2] = ffma2(u1.x, d1, a1[2]);
            a0[3] = ffma2(u1.y, d0, a0[3]);  a1[3] = ffma2(u1.y, d1, a1[3]);
        }

        #pragma unroll
        for (int j = 0; j < 4; j++) {
            float s0l, s0h, s1l, s1h;
            upk2(a0[j], s0l, s0h);   // (b_even, b_odd) logits @ v0
            upk2(a1[j], s1l, s1h);   // (b_even, b_odd) logits @ v1
            float2 r0, r1;
            r0.x = fast_sigmoid(s0l);  r0.y = fast_sigmoid(s1l);   // b_even: (v0, v1)
            r1.x = fast_sigmoid(s0h);  r1.y = fast_sigmoid(s1h);   // b_odd : (v0, v1)
            *reinterpret_cast<float2*>(&out[(size_t)(bp + 2 * j)     * VV + v0]) = r0;
            *reinterpret_cast<float2*>(&out[(size_t)(bp + 2 * j + 1) * VV + v0]) = r1;
        }
    }
}

// ---------------- launch ----------------
extern "C" void kernel_launch(void* const* d_in, const int* in_sizes, int n_in,
                              void* d_out, int out_size)
{
    (void)in_sizes; (void)n_in; (void)out_size;
    const int*   e1_idx = (const int*)  d_in[0];
    const int*   r_idx  = (const int*)  d_in[1];
    const float* E      = (const float*)d_in[2];
    const float* R      = (const float*)d_in[3];
    const float* proj   = (const float*)d_in[4];
    const int*   idx    = (const int*)  d_in[5];
    const float* g0     = (const float*)d_in[6];
    const float* b0     = (const float*)d_in[7];
    const float* m0     = (const float*)d_in[8];
    const float* v0     = (const float*)d_in[9];
    const float* g1     = (const float*)d_in[10];
    const float* b1     = (const float*)d_in[11];
    const float* m1     = (const float*)d_in[12];
    const float* v1     = (const float*)d_in[13];
    float*       out    = (float*)d_out;

    prep_kernel<<<BB, 64>>>(e1_idx, r_idx, E, R, proj, idx,
                            g0, b0, m0, v0, g1, b1, m1, v1);

    // 256 v-columns per block (128 threads x 2 adjacent v each)
    const int grid = (VV + 255) / 256;   // 1563
    main_kernel<<<grid, 128>>>(E, out);
}

// round 6
// speedup vs baseline: 1.8776x; 1.5013x over previous
#include <cuda_runtime.h>
#include <cuda_bf16.h>
#include <cstdint>
#include <cstddef>

// Problem constants (LowFER)
#define BB 256          // batch
#define VV 400000       // vocab (= 3125 * 128)
#define D1 128
#define PP 64           // D1/2
#define KK 30
#define TT 20
#define BN_EPS 1e-5f
#define FACTOR 0.040824829046386304f   // 1/sqrt(K*T)

// x as bf16, transposed [b][k], padded row stride 34 bf16 (17 u32).
// __device__ globals are zero-initialized; k=30..33 stay 0.
#define XSTR_U32 17
__device__ uint32_t g_xbf32[BB * XSTR_U32];

// ---------------- helpers ----------------
__device__ __forceinline__ uint32_t pack_bf16x2(float lo, float hi) {
    uint32_t r;
    asm("cvt.rn.bf16x2.f32 %0, %1, %2;" : "=r"(r) : "f"(hi), "f"(lo));
    return r;
}
// sigmoid via ex2 + rcp (high accuracy, 2 MUFU)
__device__ __forceinline__ float fast_sigmoid(float z) {
    float e;
    asm("ex2.approx.f32 %0, %1;" : "=f"(e) : "f"(-z * 1.4426950408889634f));
    float r;
    asm("rcp.approx.f32 %0, %1;" : "=f"(r) : "f"(1.0f + e));
    return r;
}
// m16n8k16 bf16 x bf16 -> f32 (sm_80+ base feature; fallback HMMA on sm_100)
__device__ __forceinline__ void mma_bf16(float* c, const uint32_t* a, const uint32_t* b) {
    asm volatile(
        "mma.sync.aligned.m16n8k16.row.col.f32.bf16.bf16.f32 "
        "{%0,%1,%2,%3}, {%4,%5,%6,%7}, {%8,%9}, {%0,%1,%2,%3};"
        : "+f"(c[0]), "+f"(c[1]), "+f"(c[2]), "+f"(c[3])
        : "r"(a[0]), "r"(a[1]), "r"(a[2]), "r"(a[3]), "r"(b[0]), "r"(b[1]));
}

// ---------------- Kernel 1: compute x, store as bf16 [b][k] padded ----------------
__global__ void prep_kernel(const int* __restrict__ e1_idx, const int* __restrict__ r_idx,
                            const float* __restrict__ E,   const float* __restrict__ R,
                            const float* __restrict__ proj, const int* __restrict__ idx,
                            const float* __restrict__ g0, const float* __restrict__ b0,
                            const float* __restrict__ m0, const float* __restrict__ v0,
                            const float* __restrict__ g1, const float* __restrict__ b1,
                            const float* __restrict__ m1, const float* __restrict__ v1)
{
    __shared__ float e1s[D1];
    __shared__ float rrs[D1];
    __shared__ float ses[PP];
    __shared__ float srs[PP];

    const int t = threadIdx.x;     // 0..63
    const int b = blockIdx.x;      // 0..255

    const int ei = e1_idx[b];
    const int ri = r_idx[b];

    #pragma unroll
    for (int j = 0; j < 2; j++) {
        const int d = t + j * 64;
        float ev = E[(size_t)ei * D1 + d];
        e1s[d] = (ev - m0[d]) * rsqrtf(v0[d] + BN_EPS) * g0[d] + b0[d];
        rrs[d] = R[(size_t)ri * D1 + d];
    }
    __syncthreads();

    float sa = 0.f, sb = 0.f;
    #pragma unroll 4
    for (int d = 0; d < D1; d++) {
        const float p = proj[d * PP + t];
        sa = fmaf(e1s[d], p, sa);
        sb = fmaf(rrs[d], p, sb);
    }
    ses[t] = sa;
    srs[t] = sb;
    __syncthreads();

    float x = 0.f;
    if (t < KK) {
        float y = 0.f;
        #pragma unroll
        for (int tt = 0; tt < TT; tt++) {
            const int ia = idx[(t * TT + tt) * 2 + 0];
            const int ib = idx[(t * TT + tt) * 2 + 1];
            y = fmaf(ses[ia], srs[ib], y);
        }
        y *= FACTOR;
        const float sg = (y > 0.f) ? 1.f : ((y < 0.f) ? -1.f : 0.f);
        x = sg * sqrtf(fabsf(y) + 1e-12f);
    }

    if (t < 32) {
        float ss = x * x;
        #pragma unroll
        for (int o = 16; o; o >>= 1) ss += __shfl_xor_sync(0xffffffffu, ss, o);
        const float nrm = sqrtf(ss);
        float xn = 0.f;
        if (t < KK) {
            xn = x / fmaxf(nrm, 1e-12f);
            xn = (xn - m1[t]) * rsqrtf(v1[t] + BN_EPS) * g1[t] + b1[t];
        }
        // bf16 write, transposed layout [b][k], k in [0,32); 30,31 -> 0
        __nv_bfloat16* xb = reinterpret_cast<__nv_bfloat16*>(g_xbf32);
        xb[b * (2 * XSTR_U32) + t] = __float2bfloat16(xn);
    }
}

// ---------------- Kernel 2: warp-level bf16 MMA + sigmoid epilogue ----------------
// CTA: 128 threads (4 warps). M=128 v (32 per warp), N=256 b in 4 passes of 64,
// K=32 (k 30/31 zero).  Fragments hand-built from padded smem (no ldmatrix).
__global__ __launch_bounds__(128, 3)
void mma_kernel(const float* __restrict__ E, float* __restrict__ out)
{
    __shared__ uint32_t sE32[128 * 16];        // E tile: [v][k-pairs], 8 KB
    __shared__ uint32_t sX32[BB * XSTR_U32];   // x tile: [b][k-pairs, pad 17], 17 KB

    const int tid  = threadIdx.x;
    const int wid  = tid >> 5;
    const int lane = tid & 31;
    const int grp  = lane >> 2;   // 0..7
    const int qid  = lane & 3;    // 0..3

    const int v0 = blockIdx.x * 128;

    // Build sE: one row per thread; k cols 0..29 real, 30/31 zero
    {
        const int r = tid;
        const float4* p = reinterpret_cast<const float4*>(E + (size_t)(v0 + r) * D1);
        float e[32];
        #pragma unroll
        for (int q = 0; q < 7; q++) {
            float4 f = p[q];
            e[q * 4 + 0] = f.x; e[q * 4 + 1] = f.y;
            e[q * 4 + 2] = f.z; e[q * 4 + 3] = f.w;
        }
        float2 f2 = reinterpret_cast<const float2*>(p)[14];
        e[28] = f2.x; e[29] = f2.y; e[30] = 0.f; e[31] = 0.f;
        #pragma unroll
        for (int j = 0; j < 16; j++)
            sE32[r * 16 + j] = pack_bf16x2(e[2 * j], e[2 * j + 1]);
    }
    // Copy x tile (17408 B) straight from device global
    #pragma unroll
    for (int i = tid; i < BB * XSTR_U32; i += 128)
        sX32[i] = g_xbf32[i];
    __syncthreads();

    // A fragments, persistent: [mtile][kchunk][reg]
    uint32_t a[2][2][4];
    {
        const int r0 = wid * 32 + grp;
        #pragma unroll
        for (int mt = 0; mt < 2; mt++) {
            #pragma unroll
            for (int kc = 0; kc < 2; kc++) {
                const int rr = r0 + mt * 16;
                const int cp = kc * 8 + qid;   // k-pair index
                a[mt][kc][0] = sE32[rr * 16 + cp];
                a[mt][kc][1] = sE32[(rr + 8) * 16 + cp];
                a[mt][kc][2] = sE32[rr * 16 + cp + 4];
                a[mt][kc][3] = sE32[(rr + 8) * 16 + cp + 4];
            }
        }
    }

    const int vr = v0 + wid * 32 + grp;   // c0/c1 row; +8 for c2/c3

    #pragma unroll 1
    for (int pass = 0; pass < 4; pass++) {
        const int bp = pass * 64;

        // B fragments for this 64-b slab: [ntile][kchunk][reg]
        uint32_t bf[8][2][2];
        #pragma unroll
        for (int nt = 0; nt < 8; nt++) {
            const int bcol = bp + nt * 8 + grp;
            #pragma unroll
            for (int kc = 0; kc < 2; kc++) {
                bf[nt][kc][0] = sX32[bcol * XSTR_U32 + kc * 8 + qid];
                bf[nt][kc][1] = sX32[bcol * XSTR_U32 + kc * 8 + qid + 4];
            }
        }

        float acc[2][8][4];
        #pragma unroll
        for (int mt = 0; mt < 2; mt++)
            #pragma unroll
            for (int nt = 0; nt < 8; nt++)
                #pragma unroll
                for (int j = 0; j < 4; j++) acc[mt][nt][j] = 0.f;

        #pragma unroll
        for (int kc = 0; kc < 2; kc++)
            #pragma unroll
            for (int mt = 0; mt < 2; mt++)
                #pragma unroll
                for (int nt = 0; nt < 8; nt++)
                    mma_bf16(acc[mt][nt], a[mt][kc], bf[nt][kc]);

        // Epilogue: c0:(vr, b0) c1:(vr, b0+1) c2:(vr+8, b0) c3:(vr+8, b0+1)
        #pragma unroll
        for (int mt = 0; mt < 2; mt++) {
            const int v = vr + mt * 16;
            #pragma unroll
            for (int nt = 0; nt < 8; nt++) {
                const int b0i = bp + nt * 8 + qid * 2;
                const float* c = acc[mt][nt];
                out[(size_t)b0i       * VV + v]     = fast_sigmoid(c[0]);
                out[(size_t)(b0i + 1) * VV + v]     = fast_sigmoid(c[1]);
                out[(size_t)b0i       * VV + v + 8] = fast_sigmoid(c[2]);
                out[(size_t)(b0i + 1) * VV + v + 8] = fast_sigmoid(c[3]);
            }
        }
    }
}

// ---------------- launch ----------------
extern "C" void kernel_launch(void* const* d_in, const int* in_sizes, int n_in,
                              void* d_out, int out_size)
{
    (void)in_sizes; (void)n_in; (void)out_size;
    const int*   e1_idx = (const int*)  d_in[0];
    const int*   r_idx  = (const int*)  d_in[1];
    const float* E      = (const float*)d_in[2];
    const float* R      = (const float*)d_in[3];
    const float* proj   = (const float*)d_in[4];
    const int*   idx    = (const int*)  d_in[5];
    const float* g0     = (const float*)d_in[6];
    const float* b0     = (const float*)d_in[7];
    const float* m0     = (const float*)d_in[8];
    const float* v0     = (const float*)d_in[9];
    const float* g1     = (const float*)d_in[10];
    const float* b1     = (const float*)d_in[11];
    const float* m1     = (const float*)d_in[12];
    const float* v1     = (const float*)d_in[13];
    float*       out    = (float*)d_out;

    prep_kernel<<<BB, 64>>>(e1_idx, r_idx, E, R, proj, idx,
                            g0, b0, m0, v0, g1, b1, m1, v1);

    mma_kernel<<<VV / 128, 128>>>(E, out);   // 3125 CTAs
}